// round 10
// baseline (speedup 1.0000x reference)
#include <cuda_runtime.h>
#include <math.h>

#define D 128
#define MAXN 50048
#define MAXE 600064
#define TM 32                      // rows per tile
#define SROW 257                   // tile-buffer row stride (257 % 32 == 1)
#define FUSED_SMEM ((256*128 + 2*TM*SROW) * 4)   // 196,864 B

// ---------------- device scratch (no allocations allowed) ----------------
__device__ float g_bufA[(size_t)MAXN * D];
__device__ float g_bufB[(size_t)MAXN * D];
__device__ int   g_deg[MAXN];
__device__ int   g_off[MAXN + 1];
__device__ int   g_cursor[MAXN];
__device__ int   g_csr[MAXE];
__device__ int   g_bsum[256];
__device__ float g_invdeg[MAXN];

// buffer selectors: 0 = external pointer, 1 = g_bufA, 2 = g_bufB
static __device__ __forceinline__ const float* sel_src(const float* ext, int s) {
    return (s == 0) ? ext : ((s == 1) ? g_bufA : g_bufB);
}
static __device__ __forceinline__ float* sel_dst(float* ext, int s) {
    return (s == 0) ? ext : ((s == 1) ? g_bufA : g_bufB);
}

// ---------------- packed f32x2 helpers (FFMA2: 2x fp32 FMA throughput) ----
static __device__ __forceinline__ unsigned long long pk2(float x) {
    unsigned long long r;
    asm("mov.b64 %0, {%1, %1};" : "=l"(r) : "f"(x));
    return r;
}
static __device__ __forceinline__ void ffma2(unsigned long long& d,
                                             unsigned long long a,
                                             unsigned long long b) {
    asm("fma.rn.f32x2 %0, %1, %2, %0;" : "+l"(d) : "l"(a), "l"(b));
}
static __device__ __forceinline__ float2 upk(unsigned long long v) {
    float2 r;
    asm("mov.b64 {%0, %1}, %2;" : "=f"(r.x), "=f"(r.y) : "l"(v));
    return r;
}

// ---------------- CSR build ----------------
__global__ void zero_deg_kernel(int n) {
    int i = blockIdx.x * blockDim.x + threadIdx.x;
    if (i < n) g_deg[i] = 0;
}

__global__ void count_kernel(const int* __restrict__ dst, int e) {
    int i = blockIdx.x * blockDim.x + threadIdx.x;
    if (i < e) atomicAdd(&g_deg[dst[i]], 1);
}

// per-512-block exclusive scan over degrees; also emits inv_deg = 1/max(deg,1)
__global__ void scan_block_kernel(int n) {
    __shared__ int s[512];
    int t = threadIdx.x;
    int i = blockIdx.x * 512 + t;
    int v = (i < n) ? g_deg[i] : 0;
    if (i < n) g_invdeg[i] = 1.0f / fmaxf((float)v, 1.0f);
    s[t] = v;
    __syncthreads();
    #pragma unroll
    for (int d = 1; d < 512; d <<= 1) {
        int x = (t >= d) ? s[t - d] : 0;
        __syncthreads();
        s[t] += x;
        __syncthreads();
    }
    if (i < n) g_off[i] = s[t] - v;
    if (t == 511) g_bsum[blockIdx.x] = s[511];
}

// single-block parallel exclusive scan of block sums (nb <= 128)
__global__ void scan_spine_kernel(int nb) {
    __shared__ int s[128];
    int t = threadIdx.x;
    int v = (t < nb) ? g_bsum[t] : 0;
    s[t] = v;
    __syncthreads();
    #pragma unroll
    for (int d = 1; d < 128; d <<= 1) {
        int x = (t >= d) ? s[t - d] : 0;
        __syncthreads();
        s[t] += x;
        __syncthreads();
    }
    if (t < nb) g_bsum[t] = s[t] - v;
}

__global__ void scan_add_kernel(int n, int e) {
    int i = blockIdx.x * blockDim.x + threadIdx.x;
    if (i < n) {
        int o = g_off[i] + g_bsum[i >> 9];
        g_off[i] = o;
        g_cursor[i] = o;
    } else if (i == n) {
        g_off[n] = e;
    }
}

__global__ void fill_kernel(const int* __restrict__ src, const int* __restrict__ dst, int e) {
    int i = blockIdx.x * blockDim.x + threadIdx.x;
    if (i < e) {
        int d = dst[i];
        int p = atomicAdd(&g_cursor[d], 1);
        g_csr[p] = src[i];
    }
}

// ---------------- producer: build one 32-row tile in SMEM -----------------
// buf layout: buf[m*SROW + k], k in [0,128) = mean-aggregated neighbors,
//             k in [128,256) = X row (root term). 4 producer warps, 8 rows each.
static __device__ __forceinline__ void produce_tile(
    float* __restrict__ buf, const float4* __restrict__ X4,
    int tile, int n, int pw, int lane)
{
    int mbase = pw * 8;
    #pragma unroll 1
    for (int m = mbase; m < mbase + 8; m++) {
        int row = tile * TM + m;
        if (row >= n) continue;

        int s  = __ldg(&g_off[row]);
        int e2 = __ldg(&g_off[row + 1]);
        float4 acc = make_float4(0.f, 0.f, 0.f, 0.f);
        int k = s;
        for (; k + 4 <= e2; k += 4) {
            int j0 = __ldg(&g_csr[k + 0]);
            int j1 = __ldg(&g_csr[k + 1]);
            int j2 = __ldg(&g_csr[k + 2]);
            int j3 = __ldg(&g_csr[k + 3]);
            float4 v0 = __ldg(&X4[(size_t)j0 * 32 + lane]);
            float4 v1 = __ldg(&X4[(size_t)j1 * 32 + lane]);
            float4 v2 = __ldg(&X4[(size_t)j2 * 32 + lane]);
            float4 v3 = __ldg(&X4[(size_t)j3 * 32 + lane]);
            acc.x += v0.x + v1.x + v2.x + v3.x;
            acc.y += v0.y + v1.y + v2.y + v3.y;
            acc.z += v0.z + v1.z + v2.z + v3.z;
            acc.w += v0.w + v1.w + v2.w + v3.w;
        }
        for (; k < e2; k++) {
            int j = __ldg(&g_csr[k]);
            float4 v = __ldg(&X4[(size_t)j * 32 + lane]);
            acc.x += v.x; acc.y += v.y; acc.z += v.z; acc.w += v.w;
        }
        float sc = __ldg(&g_invdeg[row]);
        float* bp = buf + m * SROW + 4 * lane;
        bp[0] = acc.x * sc;
        bp[1] = acc.y * sc;
        bp[2] = acc.z * sc;
        bp[3] = acc.w * sc;

        float4 xv = __ldg(&X4[(size_t)row * 32 + lane]);
        bp[128 + 0] = xv.x;
        bp[128 + 1] = xv.y;
        bp[128 + 2] = xv.z;
        bp[128 + 3] = xv.w;
    }
}

// ---------------- fused persistent kernel -------------------------------
// Y = ELU( mean_agg(X) @ W1 + X @ W2 + b )
// 12 warps: 8 compute (FFMA2 micro-kernel), 4 producer (gather next tile).
// Double-buffered 32-row tiles; one __syncthreads per tile.
__global__ __launch_bounds__(384, 1) void fused_layer_kernel(
    const float* __restrict__ Xext, int xsel,
    const float* __restrict__ W1, const float* __restrict__ W2,
    const float* __restrict__ bias,
    float* __restrict__ Yext, int ysel, int n, int ntiles)
{
    extern __shared__ float smem[];
    float* sW  = smem;                 // [256][128] : k<128 -> W1, else W2
    float* sB0 = smem + 256 * 128;
    float* sB1 = sB0 + TM * SROW;

    const float* X = sel_src(Xext, xsel);
    float* Y = sel_dst(Yext, ysel);
    const float4* X4 = (const float4*)X;

    int t    = threadIdx.x;
    int wid  = t >> 5;
    int lane = t & 31;
    bool is_comp = (wid < 8);

    int mrow = 0, ncol = 0;
    float b[8];

    if (is_comp) {
        // ---- weight load ONCE by compute threads (256) ----
        const float4* W1v = (const float4*)W1;
        const float4* W2v = (const float4*)W2;
        float4* sWv = (float4*)sW;
        #pragma unroll
        for (int i = 0; i < 16; i++) {
            int idx = t + i * 256;
            sWv[idx]        = __ldg(&W1v[idx]);
            sWv[idx + 4096] = __ldg(&W2v[idx]);
        }
        mrow = (t & 15) * 2;
        ncol = (t >> 4) * 8;
        #pragma unroll
        for (int j = 0; j < 8; j++) b[j] = __ldg(&bias[ncol + j]);
    } else {
        // ---- producers fill buffer 0 with the first tile meanwhile ----
        produce_tile(sB0, X4, blockIdx.x, n, wid - 8, lane);
    }
    __syncthreads();

    int p = 0;
    for (int tile = blockIdx.x; tile < ntiles; tile += gridDim.x) {
        float* cur = p ? sB1 : sB0;
        float* nxt = p ? sB0 : sB1;

        if (is_comp) {
            // ---- FFMA2 main loop over K=256 ----
            unsigned long long acc[2][4];
            #pragma unroll
            for (int r = 0; r < 2; r++)
                #pragma unroll
                for (int c = 0; c < 4; c++) acc[r][c] = 0ull;

            const float* a0p = cur + mrow * SROW;
            const float* a1p = a0p + SROW;
            const unsigned long long* wp = (const unsigned long long*)(sW + ncol);

            #pragma unroll 4
            for (int k = 0; k < 256; k++) {
                unsigned long long A0 = pk2(a0p[k]);
                unsigned long long A1 = pk2(a1p[k]);
                unsigned long long w0 = wp[0], w1 = wp[1],
                                   w2 = wp[2], w3 = wp[3];
                ffma2(acc[0][0], A0, w0); ffma2(acc[0][1], A0, w1);
                ffma2(acc[0][2], A0, w2); ffma2(acc[0][3], A0, w3);
                ffma2(acc[1][0], A1, w0); ffma2(acc[1][1], A1, w1);
                ffma2(acc[1][2], A1, w2); ffma2(acc[1][3], A1, w3);
                wp += 64;   // next k row (128 floats)
            }

            // ---- epilogue: bias + ELU + store ----
            #pragma unroll
            for (int r = 0; r < 2; r++) {
                int row = tile * TM + mrow + r;
                if (row < n) {
                    float o[8];
                    #pragma unroll
                    for (int c = 0; c < 4; c++) {
                        float2 q = upk(acc[r][c]);
                        o[2 * c]     = q.x + b[2 * c];
                        o[2 * c + 1] = q.y + b[2 * c + 1];
                    }
                    #pragma unroll
                    for (int j = 0; j < 8; j++) {
                        float v = o[j];
                        o[j] = (v > 0.f) ? v : expm1f(v);
                    }
                    float4* Yv = (float4*)(Y + (size_t)row * D + ncol);
                    Yv[0] = make_float4(o[0], o[1], o[2], o[3]);
                    Yv[1] = make_float4(o[4], o[5], o[6], o[7]);
                }
            }
        } else {
            int next = tile + gridDim.x;
            if (next < ntiles)
                produce_tile(nxt, X4, next, n, wid - 8, lane);
        }

        __syncthreads();
        p ^= 1;
    }
}

// ---------------- launch ----------------
extern "C" void kernel_launch(void* const* d_in, const int* in_sizes, int n_in,
                              void* d_out, int out_size)
{
    const float* X0    = (const float*)d_in[0];   // node_embedding [N,128]
    const int*   ei    = (const int*)  d_in[1];   // edge_index [2,E]
    const float* Wrel  = (const float*)d_in[2];   // [L,128,128]
    const float* brel  = (const float*)d_in[3];   // [L,128]
    const float* Wroot = (const float*)d_in[4];   // [L,128,128]
    float* out = (float*)d_out;

    int n = in_sizes[0] / D;
    int e = in_sizes[1] / 2;
    int L = in_sizes[2] / (D * D);

    const int* src = ei;
    const int* dst = ei + e;

    // --- CSR build (dst-sorted adjacency) ---
    zero_deg_kernel<<<(n + 255) / 256, 256>>>(n);
    count_kernel<<<(e + 255) / 256, 256>>>(dst, e);
    int nb = (n + 511) / 512;
    scan_block_kernel<<<nb, 512>>>(n);
    scan_spine_kernel<<<1, 128>>>(nb);
    scan_add_kernel<<<(n + 1 + 255) / 256, 256>>>(n, e);
    fill_kernel<<<(e + 255) / 256, 256>>>(src, dst, e);

    cudaFuncSetAttribute(fused_layer_kernel,
                         cudaFuncAttributeMaxDynamicSharedMemorySize, FUSED_SMEM);

    int nsm = 148;
    {
        int dev = 0, v = 0;
        if (cudaGetDevice(&dev) == cudaSuccess &&
            cudaDeviceGetAttribute(&v, cudaDevAttrMultiProcessorCount, dev) == cudaSuccess &&
            v > 0) nsm = v;
    }

    int ntiles = (n + TM - 1) / TM;
    int grid   = (ntiles < nsm) ? ntiles : nsm;
    if (grid < 1) grid = 1;

    int xsel = 0;
    const float* xext = X0;
    for (int l = 0; l < L; l++) {
        int ysel;
        float* yext;
        if (l == L - 1) { ysel = 0; yext = out; }
        else            { ysel = (l & 1) ? 2 : 1; yext = out; /* unused */ }

        fused_layer_kernel<<<grid, 384, FUSED_SMEM>>>(
            xext, xsel,
            Wrel + (size_t)l * D * D,
            Wroot + (size_t)l * D * D,
            brel + (size_t)l * D,
            yext, ysel, n, ntiles);

        xsel = ysel;
        xext = yext;
    }
}

// round 11
// speedup vs baseline: 1.4424x; 1.4424x over previous
#include <cuda_runtime.h>
#include <math.h>

#define D 128
#define MAXN 50048
#define MAXE 600064
#define TM 32                      // rows per tile
#define SROW 257                   // tile-buffer row stride (257 % 32 == 1)
#define FUSED_SMEM ((256*128 + 2*TM*SROW) * 4)   // 196,864 B
#define NTHREADS 512               // 8 compute warps + 8 producer warps

// ---------------- device scratch (no allocations allowed) ----------------
__device__ float g_bufA[(size_t)MAXN * D];
__device__ float g_bufB[(size_t)MAXN * D];
__device__ int   g_deg[MAXN];
__device__ int   g_off[MAXN + 1];
__device__ int   g_cursor[MAXN];
__device__ int   g_csr[MAXE];
__device__ int   g_bsum[256];
__device__ float g_invdeg[MAXN];

// buffer selectors: 0 = external pointer, 1 = g_bufA, 2 = g_bufB
static __device__ __forceinline__ const float* sel_src(const float* ext, int s) {
    return (s == 0) ? ext : ((s == 1) ? g_bufA : g_bufB);
}
static __device__ __forceinline__ float* sel_dst(float* ext, int s) {
    return (s == 0) ? ext : ((s == 1) ? g_bufA : g_bufB);
}

// ---------------- packed f32x2 helpers (FFMA2: 2x fp32 FMA throughput) ----
static __device__ __forceinline__ unsigned long long pk2(float x) {
    unsigned long long r;
    asm("mov.b64 %0, {%1, %1};" : "=l"(r) : "f"(x));
    return r;
}
static __device__ __forceinline__ void ffma2(unsigned long long& d,
                                             unsigned long long a,
                                             unsigned long long b) {
    asm("fma.rn.f32x2 %0, %1, %2, %0;" : "+l"(d) : "l"(a), "l"(b));
}
static __device__ __forceinline__ float2 upk(unsigned long long v) {
    float2 r;
    asm("mov.b64 {%0, %1}, %2;" : "=f"(r.x), "=f"(r.y) : "l"(v));
    return r;
}

// ---------------- CSR build ----------------
__global__ void zero_deg_kernel(int n) {
    int i = blockIdx.x * blockDim.x + threadIdx.x;
    if (i < n) g_deg[i] = 0;
}

__global__ void count_kernel(const int* __restrict__ dst, int e) {
    int i = blockIdx.x * blockDim.x + threadIdx.x;
    if (i < e) atomicAdd(&g_deg[dst[i]], 1);
}

// per-512-block exclusive scan over degrees; also emits inv_deg = 1/max(deg,1)
__global__ void scan_block_kernel(int n) {
    __shared__ int s[512];
    int t = threadIdx.x;
    int i = blockIdx.x * 512 + t;
    int v = (i < n) ? g_deg[i] : 0;
    if (i < n) g_invdeg[i] = 1.0f / fmaxf((float)v, 1.0f);
    s[t] = v;
    __syncthreads();
    #pragma unroll
    for (int d = 1; d < 512; d <<= 1) {
        int x = (t >= d) ? s[t - d] : 0;
        __syncthreads();
        s[t] += x;
        __syncthreads();
    }
    if (i < n) g_off[i] = s[t] - v;
    if (t == 511) g_bsum[blockIdx.x] = s[511];
}

// single-block parallel exclusive scan of block sums (nb <= 128)
__global__ void scan_spine_kernel(int nb) {
    __shared__ int s[128];
    int t = threadIdx.x;
    int v = (t < nb) ? g_bsum[t] : 0;
    s[t] = v;
    __syncthreads();
    #pragma unroll
    for (int d = 1; d < 128; d <<= 1) {
        int x = (t >= d) ? s[t - d] : 0;
        __syncthreads();
        s[t] += x;
        __syncthreads();
    }
    if (t < nb) g_bsum[t] = s[t] - v;
}

__global__ void scan_add_kernel(int n, int e) {
    int i = blockIdx.x * blockDim.x + threadIdx.x;
    if (i < n) {
        int o = g_off[i] + g_bsum[i >> 9];
        g_off[i] = o;
        g_cursor[i] = o;
    } else if (i == n) {
        g_off[n] = e;
    }
}

__global__ void fill_kernel(const int* __restrict__ src, const int* __restrict__ dst, int e) {
    int i = blockIdx.x * blockDim.x + threadIdx.x;
    if (i < e) {
        int d = dst[i];
        int p = atomicAdd(&g_cursor[d], 1);
        g_csr[p] = src[i];
    }
}

// ---------------- producer: build rows of a 32-row tile in SMEM ------------
// buf layout: buf[m*SROW + k], k in [0,128) = mean-aggregated neighbors,
//             k in [128,256) = X row (root term).
// 8 producer warps, 4 rows each. Index loads software-pipelined so the
// csr-index latency overlaps the feature-gather latency.
static __device__ __forceinline__ void produce_tile(
    float* __restrict__ buf, const float4* __restrict__ X4,
    int tile, int n, int pw, int lane)
{
    int mbase = pw * 4;
    #pragma unroll 1
    for (int m = mbase; m < mbase + 4; m++) {
        int row = tile * TM + m;
        if (row >= n) continue;

        int s  = __ldg(&g_off[row]);
        int e2 = __ldg(&g_off[row + 1]);
        float4 acc = make_float4(0.f, 0.f, 0.f, 0.f);
        int k = s;

        if (k + 4 <= e2) {
            // prime the pipeline with the first index group
            int j0 = __ldg(&g_csr[k + 0]);
            int j1 = __ldg(&g_csr[k + 1]);
            int j2 = __ldg(&g_csr[k + 2]);
            int j3 = __ldg(&g_csr[k + 3]);
            k += 4;
            #pragma unroll 1
            while (k + 4 <= e2) {
                // prefetch next indices (overlaps with gathers below)
                int n0 = __ldg(&g_csr[k + 0]);
                int n1 = __ldg(&g_csr[k + 1]);
                int n2 = __ldg(&g_csr[k + 2]);
                int n3 = __ldg(&g_csr[k + 3]);
                float4 v0 = __ldg(&X4[(size_t)j0 * 32 + lane]);
                float4 v1 = __ldg(&X4[(size_t)j1 * 32 + lane]);
                float4 v2 = __ldg(&X4[(size_t)j2 * 32 + lane]);
                float4 v3 = __ldg(&X4[(size_t)j3 * 32 + lane]);
                acc.x += v0.x + v1.x + v2.x + v3.x;
                acc.y += v0.y + v1.y + v2.y + v3.y;
                acc.z += v0.z + v1.z + v2.z + v3.z;
                acc.w += v0.w + v1.w + v2.w + v3.w;
                j0 = n0; j1 = n1; j2 = n2; j3 = n3;
                k += 4;
            }
            // drain the primed group
            float4 v0 = __ldg(&X4[(size_t)j0 * 32 + lane]);
            float4 v1 = __ldg(&X4[(size_t)j1 * 32 + lane]);
            float4 v2 = __ldg(&X4[(size_t)j2 * 32 + lane]);
            float4 v3 = __ldg(&X4[(size_t)j3 * 32 + lane]);
            acc.x += v0.x + v1.x + v2.x + v3.x;
            acc.y += v0.y + v1.y + v2.y + v3.y;
            acc.z += v0.z + v1.z + v2.z + v3.z;
            acc.w += v0.w + v1.w + v2.w + v3.w;
        }
        #pragma unroll 1
        for (; k < e2; k++) {
            int j = __ldg(&g_csr[k]);
            float4 v = __ldg(&X4[(size_t)j * 32 + lane]);
            acc.x += v.x; acc.y += v.y; acc.z += v.z; acc.w += v.w;
        }

        float sc = __ldg(&g_invdeg[row]);
        float* bp = buf + m * SROW + 4 * lane;
        bp[0] = acc.x * sc;
        bp[1] = acc.y * sc;
        bp[2] = acc.z * sc;
        bp[3] = acc.w * sc;

        float4 xv = __ldg(&X4[(size_t)row * 32 + lane]);
        bp[128 + 0] = xv.x;
        bp[128 + 1] = xv.y;
        bp[128 + 2] = xv.z;
        bp[128 + 3] = xv.w;
    }
}

// ---------------- fused persistent kernel -------------------------------
// Y = ELU( mean_agg(X) @ W1 + X @ W2 + b )
// 16 warps: 8 compute (FFMA2 micro-kernel), 8 producer (gather next tile).
// Double-buffered 32-row tiles; one __syncthreads per tile.
__global__ __launch_bounds__(NTHREADS, 1) void fused_layer_kernel(
    const float* __restrict__ Xext, int xsel,
    const float* __restrict__ W1, const float* __restrict__ W2,
    const float* __restrict__ bias,
    float* __restrict__ Yext, int ysel, int n, int ntiles)
{
    extern __shared__ float smem[];
    float* sW  = smem;                 // [256][128] : k<128 -> W1, else W2
    float* sB0 = smem + 256 * 128;
    float* sB1 = sB0 + TM * SROW;

    const float* X = sel_src(Xext, xsel);
    float* Y = sel_dst(Yext, ysel);
    const float4* X4 = (const float4*)X;

    int t    = threadIdx.x;
    int wid  = t >> 5;
    int lane = t & 31;
    bool is_comp = (wid < 8);

    int mrow = 0, ncol = 0;
    float b[8];

    if (is_comp) {
        // ---- weight load ONCE by compute threads (t = 0..255) ----
        const float4* W1v = (const float4*)W1;
        const float4* W2v = (const float4*)W2;
        float4* sWv = (float4*)sW;
        #pragma unroll
        for (int i = 0; i < 16; i++) {
            int idx = t + i * 256;
            sWv[idx]        = __ldg(&W1v[idx]);
            sWv[idx + 4096] = __ldg(&W2v[idx]);
        }
        mrow = (t & 15) * 2;
        ncol = (t >> 4) * 8;
        #pragma unroll
        for (int j = 0; j < 8; j++) b[j] = __ldg(&bias[ncol + j]);
    } else {
        // ---- producers fill buffer 0 with the first tile meanwhile ----
        produce_tile(sB0, X4, blockIdx.x, n, wid - 8, lane);
    }
    __syncthreads();

    int p = 0;
    for (int tile = blockIdx.x; tile < ntiles; tile += gridDim.x) {
        float* cur = p ? sB1 : sB0;
        float* nxt = p ? sB0 : sB1;

        if (is_comp) {
            // ---- FFMA2 main loop over K=256 ----
            unsigned long long acc[2][4];
            #pragma unroll
            for (int r = 0; r < 2; r++)
                #pragma unroll
                for (int c = 0; c < 4; c++) acc[r][c] = 0ull;

            const float* a0p = cur + mrow * SROW;
            const float* a1p = a0p + SROW;
            const unsigned long long* wp = (const unsigned long long*)(sW + ncol);

            #pragma unroll 4
            for (int k = 0; k < 256; k++) {
                unsigned long long A0 = pk2(a0p[k]);
                unsigned long long A1 = pk2(a1p[k]);
                unsigned long long w0 = wp[0], w1 = wp[1],
                                   w2 = wp[2], w3 = wp[3];
                ffma2(acc[0][0], A0, w0); ffma2(acc[0][1], A0, w1);
                ffma2(acc[0][2], A0, w2); ffma2(acc[0][3], A0, w3);
                ffma2(acc[1][0], A1, w0); ffma2(acc[1][1], A1, w1);
                ffma2(acc[1][2], A1, w2); ffma2(acc[1][3], A1, w3);
                wp += 64;   // next k row (128 floats)
            }

            // ---- epilogue: bias + ELU + store ----
            #pragma unroll
            for (int r = 0; r < 2; r++) {
                int row = tile * TM + mrow + r;
                if (row < n) {
                    float o[8];
                    #pragma unroll
                    for (int c = 0; c < 4; c++) {
                        float2 q = upk(acc[r][c]);
                        o[2 * c]     = q.x + b[2 * c];
                        o[2 * c + 1] = q.y + b[2 * c + 1];
                    }
                    #pragma unroll
                    for (int j = 0; j < 8; j++) {
                        float v = o[j];
                        o[j] = (v > 0.f) ? v : expm1f(v);
                    }
                    float4* Yv = (float4*)(Y + (size_t)row * D + ncol);
                    Yv[0] = make_float4(o[0], o[1], o[2], o[3]);
                    Yv[1] = make_float4(o[4], o[5], o[6], o[7]);
                }
            }
        } else {
            int next = tile + gridDim.x;
            if (next < ntiles)
                produce_tile(nxt, X4, next, n, wid - 8, lane);
        }

        __syncthreads();
        p ^= 1;
    }
}

// ---------------- launch ----------------
extern "C" void kernel_launch(void* const* d_in, const int* in_sizes, int n_in,
                              void* d_out, int out_size)
{
    const float* X0    = (const float*)d_in[0];   // node_embedding [N,128]
    const int*   ei    = (const int*)  d_in[1];   // edge_index [2,E]
    const float* Wrel  = (const float*)d_in[2];   // [L,128,128]
    const float* brel  = (const float*)d_in[3];   // [L,128]
    const float* Wroot = (const float*)d_in[4];   // [L,128,128]
    float* out = (float*)d_out;

    int n = in_sizes[0] / D;
    int e = in_sizes[1] / 2;
    int L = in_sizes[2] / (D * D);

    const int* src = ei;
    const int* dst = ei + e;

    // --- CSR build (dst-sorted adjacency) ---
    zero_deg_kernel<<<(n + 255) / 256, 256>>>(n);
    count_kernel<<<(e + 255) / 256, 256>>>(dst, e);
    int nb = (n + 511) / 512;
    scan_block_kernel<<<nb, 512>>>(n);
    scan_spine_kernel<<<1, 128>>>(nb);
    scan_add_kernel<<<(n + 1 + 255) / 256, 256>>>(n, e);
    fill_kernel<<<(e + 255) / 256, 256>>>(src, dst, e);

    cudaFuncSetAttribute(fused_layer_kernel,
                         cudaFuncAttributeMaxDynamicSharedMemorySize, FUSED_SMEM);

    int nsm = 148;
    {
        int dev = 0, v = 0;
        if (cudaGetDevice(&dev) == cudaSuccess &&
            cudaDeviceGetAttribute(&v, cudaDevAttrMultiProcessorCount, dev) == cudaSuccess &&
            v > 0) nsm = v;
    }

    int ntiles = (n + TM - 1) / TM;
    int grid   = (ntiles < nsm) ? ntiles : nsm;
    if (grid < 1) grid = 1;

    int xsel = 0;
    const float* xext = X0;
    for (int l = 0; l < L; l++) {
        int ysel;
        float* yext;
        if (l == L - 1) { ysel = 0; yext = out; }
        else            { ysel = (l & 1) ? 2 : 1; yext = out; /* unused */ }

        fused_layer_kernel<<<grid, NTHREADS, FUSED_SMEM>>>(
            xext, xsel,
            Wrel + (size_t)l * D * D,
            Wroot + (size_t)l * D * D,
            brel + (size_t)l * D,
            yext, ysel, n, ntiles);

        xsel = ysel;
        xext = yext;
    }
}

// round 12
// speedup vs baseline: 1.4478x; 1.0038x over previous
#include <cuda_runtime.h>
#include <math.h>

#define D 128
#define MAXN 50048
#define MAXE 600064
#define TM 32                      // rows per tile
#define SROW 257                   // tile-buffer row stride (257 % 32 == 1)
#define FUSED_SMEM ((256*128 + 2*TM*SROW) * 4)   // 196,864 B
#define NTHREADS 512               // 8 compute warps + 8 producer warps

// ---------------- device scratch (no allocations allowed) ----------------
__device__ float g_bufA[(size_t)MAXN * D];
__device__ float g_bufB[(size_t)MAXN * D];
__device__ int   g_deg[MAXN];
__device__ int   g_off[MAXN + 1];
__device__ int   g_cursor[MAXN];
__device__ int   g_csr[MAXE];
__device__ int   g_bsum[256];
__device__ float g_invdeg[MAXN];

// buffer selectors: 0 = external pointer, 1 = g_bufA, 2 = g_bufB
static __device__ __forceinline__ const float* sel_src(const float* ext, int s) {
    return (s == 0) ? ext : ((s == 1) ? g_bufA : g_bufB);
}
static __device__ __forceinline__ float* sel_dst(float* ext, int s) {
    return (s == 0) ? ext : ((s == 1) ? g_bufA : g_bufB);
}

// ---------------- packed f32x2 helpers (FFMA2: 2x fp32 FMA throughput) ----
static __device__ __forceinline__ unsigned long long pk2(float x) {
    unsigned long long r;
    asm("mov.b64 %0, {%1, %1};" : "=l"(r) : "f"(x));
    return r;
}
static __device__ __forceinline__ void ffma2(unsigned long long& d,
                                             unsigned long long a,
                                             unsigned long long b) {
    asm("fma.rn.f32x2 %0, %1, %2, %0;" : "+l"(d) : "l"(a), "l"(b));
}
static __device__ __forceinline__ float2 upk(unsigned long long v) {
    float2 r;
    asm("mov.b64 {%0, %1}, %2;" : "=f"(r.x), "=f"(r.y) : "l"(v));
    return r;
}

// ---------------- CSR build ----------------
__global__ void zero_deg_kernel(int n) {
    int i = blockIdx.x * blockDim.x + threadIdx.x;
    if (i < n) g_deg[i] = 0;
}

__global__ void count_kernel(const int* __restrict__ dst, int e) {
    int i = blockIdx.x * blockDim.x + threadIdx.x;
    if (i < e) atomicAdd(&g_deg[dst[i]], 1);
}

// per-512-block exclusive scan over degrees; also emits inv_deg = 1/max(deg,1)
__global__ void scan_block_kernel(int n) {
    __shared__ int s[512];
    int t = threadIdx.x;
    int i = blockIdx.x * 512 + t;
    int v = (i < n) ? g_deg[i] : 0;
    if (i < n) g_invdeg[i] = 1.0f / fmaxf((float)v, 1.0f);
    s[t] = v;
    __syncthreads();
    #pragma unroll
    for (int d = 1; d < 512; d <<= 1) {
        int x = (t >= d) ? s[t - d] : 0;
        __syncthreads();
        s[t] += x;
        __syncthreads();
    }
    if (i < n) g_off[i] = s[t] - v;
    if (t == 511) g_bsum[blockIdx.x] = s[511];
}

// single-block parallel exclusive scan of block sums (nb <= 128)
__global__ void scan_spine_kernel(int nb) {
    __shared__ int s[128];
    int t = threadIdx.x;
    int v = (t < nb) ? g_bsum[t] : 0;
    s[t] = v;
    __syncthreads();
    #pragma unroll
    for (int d = 1; d < 128; d <<= 1) {
        int x = (t >= d) ? s[t - d] : 0;
        __syncthreads();
        s[t] += x;
        __syncthreads();
    }
    if (t < nb) g_bsum[t] = s[t] - v;
}

__global__ void scan_add_kernel(int n, int e) {
    int i = blockIdx.x * blockDim.x + threadIdx.x;
    if (i < n) {
        int o = g_off[i] + g_bsum[i >> 9];
        g_off[i] = o;
        g_cursor[i] = o;
    } else if (i == n) {
        g_off[n] = e;
    }
}

__global__ void fill_kernel(const int* __restrict__ src, const int* __restrict__ dst, int e) {
    int i = blockIdx.x * blockDim.x + threadIdx.x;
    if (i < e) {
        int d = dst[i];
        int p = atomicAdd(&g_cursor[d], 1);
        g_csr[p] = src[i];
    }
}

// ---------------- producer: build rows of a 32-row tile in SMEM ------------
// buf layout: buf[m*SROW + k], k in [0,128) = mean-aggregated neighbors,
//             k in [128,256) = X row (root term).
// 8 producer warps, 4 rows each. ALL 4 rows advance together per iteration:
// 16 gathers (8 KB) in flight per warp, with next iteration's 16 CSR
// indices prefetched concurrently. Finished rows predicate off (warp-
// uniform guards).
static __device__ __forceinline__ void produce_tile(
    float* __restrict__ buf, const float4* __restrict__ X4,
    int tile, int n, int pw, int lane)
{
    int base = tile * TM + pw * 4;

    int kk[4], ee[4];
    float4 acc[4], xv[4];
    #pragma unroll
    for (int i = 0; i < 4; i++) {
        int row = base + i;
        if (row < n) {
            kk[i] = __ldg(&g_off[row]);
            ee[i] = __ldg(&g_off[row + 1]);
            xv[i] = __ldg(&X4[(size_t)row * 32 + lane]);   // root term, early
        } else {
            kk[i] = 0; ee[i] = 0;
            xv[i] = make_float4(0.f, 0.f, 0.f, 0.f);
        }
        acc[i] = make_float4(0.f, 0.f, 0.f, 0.f);
    }

    // current index group: 4 slots per row, -1 = invalid
    int jc[16];
    #pragma unroll
    for (int i = 0; i < 4; i++)
        #pragma unroll
        for (int s = 0; s < 4; s++) {
            int pos = kk[i] + s;
            jc[i * 4 + s] = (pos < ee[i]) ? __ldg(&g_csr[pos]) : -1;
        }

    for (;;) {
        int more = 0;
        #pragma unroll
        for (int i = 0; i < 4; i++) more |= (kk[i] + 4 < ee[i]);

        // prefetch next index group (overlaps the gathers below)
        int jn[16];
        #pragma unroll
        for (int i = 0; i < 4; i++)
            #pragma unroll
            for (int s = 0; s < 4; s++) {
                int pos = kk[i] + 4 + s;
                jn[i * 4 + s] = (more && pos < ee[i]) ? __ldg(&g_csr[pos]) : -1;
            }

        // 16 gathers in flight (4 rows x 4 slots)
        #pragma unroll
        for (int i = 0; i < 4; i++)
            #pragma unroll
            for (int s = 0; s < 4; s++) {
                int jj = jc[i * 4 + s];
                if (jj >= 0) {
                    float4 v = __ldg(&X4[(size_t)jj * 32 + lane]);
                    acc[i].x += v.x; acc[i].y += v.y;
                    acc[i].z += v.z; acc[i].w += v.w;
                }
            }

        #pragma unroll
        for (int i = 0; i < 4; i++) kk[i] += 4;
        if (!more) break;
        #pragma unroll
        for (int s = 0; s < 16; s++) jc[s] = jn[s];
    }

    // epilogue: scale + store (conflict-free STS pattern: lanes vary columns)
    #pragma unroll
    for (int i = 0; i < 4; i++) {
        int row = base + i;
        if (row < n) {
            float sc = __ldg(&g_invdeg[row]);
            float* bp = buf + (pw * 4 + i) * SROW + 4 * lane;
            bp[0] = acc[i].x * sc;
            bp[1] = acc[i].y * sc;
            bp[2] = acc[i].z * sc;
            bp[3] = acc[i].w * sc;
            bp[128 + 0] = xv[i].x;
            bp[128 + 1] = xv[i].y;
            bp[128 + 2] = xv[i].z;
            bp[128 + 3] = xv[i].w;
        }
    }
}

// ---------------- fused persistent kernel -------------------------------
// Y = ELU( mean_agg(X) @ W1 + X @ W2 + b )
// 16 warps: 8 compute (FFMA2 micro-kernel), 8 producer (gather next tile).
// Double-buffered 32-row tiles; one __syncthreads per tile.
__global__ __launch_bounds__(NTHREADS, 1) void fused_layer_kernel(
    const float* __restrict__ Xext, int xsel,
    const float* __restrict__ W1, const float* __restrict__ W2,
    const float* __restrict__ bias,
    float* __restrict__ Yext, int ysel, int n, int ntiles)
{
    extern __shared__ float smem[];
    float* sW  = smem;                 // [256][128] : k<128 -> W1, else W2
    float* sB0 = smem + 256 * 128;
    float* sB1 = sB0 + TM * SROW;

    const float* X = sel_src(Xext, xsel);
    float* Y = sel_dst(Yext, ysel);
    const float4* X4 = (const float4*)X;

    int t    = threadIdx.x;
    int wid  = t >> 5;
    int lane = t & 31;
    bool is_comp = (wid < 8);

    int mrow = 0, ncol = 0;
    float b[8];

    if (is_comp) {
        // ---- weight load ONCE by compute threads (t = 0..255) ----
        const float4* W1v = (const float4*)W1;
        const float4* W2v = (const float4*)W2;
        float4* sWv = (float4*)sW;
        #pragma unroll
        for (int i = 0; i < 16; i++) {
            int idx = t + i * 256;
            sWv[idx]        = __ldg(&W1v[idx]);
            sWv[idx + 4096] = __ldg(&W2v[idx]);
        }
        mrow = (t & 15) * 2;
        ncol = (t >> 4) * 8;
        #pragma unroll
        for (int j = 0; j < 8; j++) b[j] = __ldg(&bias[ncol + j]);
    } else {
        // ---- producers fill buffer 0 with the first tile meanwhile ----
        produce_tile(sB0, X4, blockIdx.x, n, wid - 8, lane);
    }
    __syncthreads();

    int p = 0;
    for (int tile = blockIdx.x; tile < ntiles; tile += gridDim.x) {
        float* cur = p ? sB1 : sB0;
        float* nxt = p ? sB0 : sB1;

        if (is_comp) {
            // ---- FFMA2 main loop over K=256 ----
            unsigned long long acc[2][4];
            #pragma unroll
            for (int r = 0; r < 2; r++)
                #pragma unroll
                for (int c = 0; c < 4; c++) acc[r][c] = 0ull;

            const float* a0p = cur + mrow * SROW;
            const float* a1p = a0p + SROW;
            const unsigned long long* wp = (const unsigned long long*)(sW + ncol);

            #pragma unroll 4
            for (int k = 0; k < 256; k++) {
                unsigned long long A0 = pk2(a0p[k]);
                unsigned long long A1 = pk2(a1p[k]);
                unsigned long long w0 = wp[0], w1 = wp[1],
                                   w2 = wp[2], w3 = wp[3];
                ffma2(acc[0][0], A0, w0); ffma2(acc[0][1], A0, w1);
                ffma2(acc[0][2], A0, w2); ffma2(acc[0][3], A0, w3);
                ffma2(acc[1][0], A1, w0); ffma2(acc[1][1], A1, w1);
                ffma2(acc[1][2], A1, w2); ffma2(acc[1][3], A1, w3);
                wp += 64;   // next k row (128 floats)
            }

            // ---- epilogue: bias + ELU + store ----
            #pragma unroll
            for (int r = 0; r < 2; r++) {
                int row = tile * TM + mrow + r;
                if (row < n) {
                    float o[8];
                    #pragma unroll
                    for (int c = 0; c < 4; c++) {
                        float2 q = upk(acc[r][c]);
                        o[2 * c]     = q.x + b[2 * c];
                        o[2 * c + 1] = q.y + b[2 * c + 1];
                    }
                    #pragma unroll
                    for (int j = 0; j < 8; j++) {
                        float v = o[j];
                        o[j] = (v > 0.f) ? v : expm1f(v);
                    }
                    float4* Yv = (float4*)(Y + (size_t)row * D + ncol);
                    Yv[0] = make_float4(o[0], o[1], o[2], o[3]);
                    Yv[1] = make_float4(o[4], o[5], o[6], o[7]);
                }
            }
        } else {
            int next = tile + gridDim.x;
            if (next < ntiles)
                produce_tile(nxt, X4, next, n, wid - 8, lane);
        }

        __syncthreads();
        p ^= 1;
    }
}

// ---------------- launch ----------------
extern "C" void kernel_launch(void* const* d_in, const int* in_sizes, int n_in,
                              void* d_out, int out_size)
{
    const float* X0    = (const float*)d_in[0];   // node_embedding [N,128]
    const int*   ei    = (const int*)  d_in[1];   // edge_index [2,E]
    const float* Wrel  = (const float*)d_in[2];   // [L,128,128]
    const float* brel  = (const float*)d_in[3];   // [L,128]
    const float* Wroot = (const float*)d_in[4];   // [L,128,128]
    float* out = (float*)d_out;

    int n = in_sizes[0] / D;
    int e = in_sizes[1] / 2;
    int L = in_sizes[2] / (D * D);

    const int* src = ei;
    const int* dst = ei + e;

    // --- CSR build (dst-sorted adjacency) ---
    zero_deg_kernel<<<(n + 255) / 256, 256>>>(n);
    count_kernel<<<(e + 255) / 256, 256>>>(dst, e);
    int nb = (n + 511) / 512;
    scan_block_kernel<<<nb, 512>>>(n);
    scan_spine_kernel<<<1, 128>>>(nb);
    scan_add_kernel<<<(n + 1 + 255) / 256, 256>>>(n, e);
    fill_kernel<<<(e + 255) / 256, 256>>>(src, dst, e);

    cudaFuncSetAttribute(fused_layer_kernel,
                         cudaFuncAttributeMaxDynamicSharedMemorySize, FUSED_SMEM);

    int nsm = 148;
    {
        int dev = 0, v = 0;
        if (cudaGetDevice(&dev) == cudaSuccess &&
            cudaDeviceGetAttribute(&v, cudaDevAttrMultiProcessorCount, dev) == cudaSuccess &&
            v > 0) nsm = v;
    }

    int ntiles = (n + TM - 1) / TM;
    int grid   = (ntiles < nsm) ? ntiles : nsm;
    if (grid < 1) grid = 1;

    int xsel = 0;
    const float* xext = X0;
    for (int l = 0; l < L; l++) {
        int ysel;
        float* yext;
        if (l == L - 1) { ysel = 0; yext = out; }
        else            { ysel = (l & 1) ? 2 : 1; yext = out; /* unused */ }

        fused_layer_kernel<<<grid, NTHREADS, FUSED_SMEM>>>(
            xext, xsel,
            Wrel + (size_t)l * D * D,
            Wroot + (size_t)l * D * D,
            brel + (size_t)l * D,
            yext, ysel, n, ntiles);

        xsel = ysel;
        xext = yext;
    }
}